// round 11
// baseline (speedup 1.0000x reference)
#include <cuda_runtime.h>
#include <cuda_bf16.h>

#define NN 16500
#define NE 100000
#define KT 3
#define GEN_EPS 1e-7f
#define BN_EPS 1e-5f

// ---------------- scratch ----------------
__device__ int   d_cnt[KT][NN];          // static zero-init; re-zeroed by k_fill
__device__ int   d_off[KT][NN + 1];
__device__ int   d_cur[KT][NN];
__device__ int   d_eid[KT][NE];
__device__ float d_agg[KT][NN * 256];
__device__ float d_hh[KT][NN * 512];
__device__ float d_xcur[NN * 256];
__device__ float d_cs[KT * 512], d_css[KT * 512];
__device__ float d_scale[KT * 512], d_shift[KT * 512];
__device__ unsigned d_wa_pk[KT * 256 * 512];   // packed (hi|lo) bf16 Wa
__device__ unsigned d_wb_pk[KT * 512 * 256];   // packed (hi|lo) bf16 Wb

// ---------------- CSR build ----------------
__global__ void k_count(const int* __restrict__ ei) {
    int i = blockIdx.x * blockDim.x + threadIdx.x;
    if (i >= KT * NE) return;
    int k = i / NE, e = i % NE;
    atomicAdd(&d_cnt[k][ei[k * 2 * NE + NE + e]], 1);
}

__global__ void k_scan() {
    __shared__ int sh[1024];
    int k = blockIdx.x, tid = threadIdx.x;
    int carry = 0;
    if (tid == 0) d_off[k][0] = 0;
    for (int base = 0; base < NN; base += 1024) {
        int i = base + tid;
        int v = (i < NN) ? d_cnt[k][i] : 0;
        sh[tid] = v;
        __syncthreads();
        for (int o = 1; o < 1024; o <<= 1) {
            int t = (tid >= o) ? sh[tid - o] : 0;
            __syncthreads();
            sh[tid] += t;
            __syncthreads();
        }
        int inc = sh[tid];
        int tot = sh[1023];
        if (i < NN) {
            d_off[k][i + 1] = carry + inc;
            d_cur[k][i]     = carry + inc - v;
        }
        __syncthreads();
        carry += tot;
    }
}

__global__ void k_fill(const int* __restrict__ ei) {
    int i = blockIdx.x * blockDim.x + threadIdx.x;
    if (i < KT * NE) {
        int k = i / NE, e = i % NE;
        int pos = atomicAdd(&d_cur[k][ei[k * 2 * NE + NE + e]], 1);
        d_eid[k][pos] = e;
    }
    if (i < KT * NN) ((int*)d_cnt)[i] = 0;   // re-zero for next call
}

// ---------------- weight pre-split: f32 -> packed (hi|lo) bf16 ----------------
__device__ __forceinline__ void split_bf16(float v, __nv_bfloat16& hi,
                                           __nv_bfloat16& lo) {
    hi = __float2bfloat16(v);
    lo = __float2bfloat16(v - __bfloat162float(hi));
}

__global__ void k_wsplit(const float* __restrict__ W, unsigned* __restrict__ out,
                         int total) {
    int i = blockIdx.x * blockDim.x + threadIdx.x;
    if (i >= total) return;
    __nv_bfloat16 hi, lo;
    split_bf16(W[i], hi, lo);
    out[i] = (unsigned)__bfloat16_as_ushort(hi) |
             ((unsigned)__bfloat16_as_ushort(lo) << 16);
}

// ---- batched GENConv aggregation: NO-MAX softmax (values >=0, bounded) ----
__global__ void k_aggr(const float* __restrict__ xin,
                       const int* __restrict__ ei,
                       const float* __restrict__ ea,
                       const float* __restrict__ WeB,
                       const float* __restrict__ beB,
                       int ci) {
    __shared__ int   s_src[192];
    __shared__ float s_a[192];
    int n = blockIdx.x, k = blockIdx.y;
    int tid = threadIdx.x;

    if (n == 0) {   // fold BN-stat zeroing (before k_gemm1 atomics)
        for (int i = tid; i < 512; i += blockDim.x) {
            d_cs[k * 512 + i] = 0.f;
            d_css[k * 512 + i] = 0.f;
        }
    }

    int j0  = d_off[k][n];
    int deg = d_off[k][n + 1] - j0;
    int cap = min(deg, 192);
    const int*   src = ei + k * 2 * NE;
    const float* eak = ea + k * NE;
    for (int j = tid; j < cap; j += blockDim.x) {
        int e = d_eid[k][j0 + j];
        s_src[j] = src[e];
        s_a[j]   = eak[e];
    }
    __syncthreads();

    int c = tid;
    if (c >= ci) return;
    float we = WeB[k * ci + c], bec = beB[k * ci + c];
    float xn = xin[n * ci + c];
    // exp without max-subtraction: u in [eps, ~tens] -> e^u safe in fp32
    float u0 = fmaxf(xn + we + bec, 0.f) + GEN_EPS;   // self loop (ea = 1)
    float den = __expf(u0);
    float ws  = u0 * den;
#pragma unroll 4
    for (int j = 0; j < cap; j++) {   // fully independent iterations
        float u = fmaxf(xin[s_src[j] * ci + c] + s_a[j] * we + bec, 0.f) + GEN_EPS;
        float e = __expf(u);
        den += e;
        ws = fmaf(u, e, ws);
    }
    for (int jj = cap; jj < deg; jj++) {   // overflow tail (deg>192: ~never)
        int e0 = d_eid[k][j0 + jj];
        float u = fmaxf(xin[src[e0] * ci + c] + eak[e0] * we + bec, 0.f) + GEN_EPS;
        float e = __expf(u);
        den += e;
        ws = fmaf(u, e, ws);
    }
    d_agg[k][n * ci + c] = ws / den + xn;
}

// ---------------- bf16 split-2 tensor-core GEMM machinery ----------------
#define BM 128
#define BN 128
#define BK 32
#define BKP 40

__device__ __forceinline__ void mma_bf16(float* c, const unsigned* a,
                                         const unsigned* b) {
    asm volatile(
        "mma.sync.aligned.m16n8k16.row.col.f32.bf16.bf16.f32 "
        "{%0,%1,%2,%3}, {%4,%5,%6,%7}, {%8,%9}, {%0,%1,%2,%3};\n"
        : "+f"(c[0]), "+f"(c[1]), "+f"(c[2]), "+f"(c[3])
        : "r"(a[0]), "r"(a[1]), "r"(a[2]), "r"(a[3]), "r"(b[0]), "r"(b[1]));
}

__device__ __forceinline__ void mma_slab(
    const __nv_bfloat16 (*Ah)[BKP], const __nv_bfloat16 (*Al)[BKP],
    const __nv_bfloat16 (*Bh)[BKP], const __nv_bfloat16 (*Bl)[BKP],
    float acc[4][4][4], int wm, int wn, int gid, int tig) {
#pragma unroll
    for (int ks = 0; ks < 2; ks++) {
        int kb = ks * 16 + 2 * tig;
        unsigned bh[4][2], bl[4][2];
#pragma unroll
        for (int nj = 0; nj < 4; nj++) {
            int nn2 = wn * 32 + nj * 8 + gid;
            bh[nj][0] = *(const unsigned*)&Bh[nn2][kb];
            bh[nj][1] = *(const unsigned*)&Bh[nn2][kb + 8];
            bl[nj][0] = *(const unsigned*)&Bl[nn2][kb];
            bl[nj][1] = *(const unsigned*)&Bl[nn2][kb + 8];
        }
#pragma unroll
        for (int mi = 0; mi < 4; mi++) {
            int r0 = wm * 64 + mi * 16 + gid;
            unsigned ah[4], al[4];
            ah[0] = *(const unsigned*)&Ah[r0][kb];
            ah[1] = *(const unsigned*)&Ah[r0 + 8][kb];
            ah[2] = *(const unsigned*)&Ah[r0][kb + 8];
            ah[3] = *(const unsigned*)&Ah[r0 + 8][kb + 8];
            al[0] = *(const unsigned*)&Al[r0][kb];
            al[1] = *(const unsigned*)&Al[r0 + 8][kb];
            al[2] = *(const unsigned*)&Al[r0][kb + 8];
            al[3] = *(const unsigned*)&Al[r0 + 8][kb + 8];
#pragma unroll
            for (int nj = 0; nj < 4; nj++) {
                mma_bf16(acc[mi][nj], ah, bh[nj]);
                mma_bf16(acc[mi][nj], ah, bl[nj]);
                mma_bf16(acc[mi][nj], al, bh[nj]);
            }
        }
    }
}

// store A regs (f32) split+packed into Ah/Al
__device__ __forceinline__ void sts_A(const float* aR, __nv_bfloat16 (*Ah)[BKP],
                                      __nv_bfloat16 (*Al)[BKP], int arow, int akq) {
#pragma unroll
    for (int p = 0; p < 8; p++) {
        __nv_bfloat16 h0, l0, h1, l1;
        split_bf16(aR[2 * p], h0, l0);
        split_bf16(aR[2 * p + 1], h1, l1);
        *(unsigned*)&Ah[arow][akq + 2 * p] =
            (unsigned)__bfloat16_as_ushort(h0) |
            ((unsigned)__bfloat16_as_ushort(h1) << 16);
        *(unsigned*)&Al[arow][akq + 2 * p] =
            (unsigned)__bfloat16_as_ushort(l0) |
            ((unsigned)__bfloat16_as_ushort(l1) << 16);
    }
}

// store packed-W regs into Bh/Bl via byte-permute
__device__ __forceinline__ void sts_B(const unsigned* wR, __nv_bfloat16 (*Bh)[BKP],
                                      __nv_bfloat16 (*Bl)[BKP], int bn_, int bkh) {
#pragma unroll
    for (int p = 0; p < 8; p++) {
        unsigned a = wR[2 * p], b = wR[2 * p + 1];
        *(unsigned*)&Bh[bn_][bkh + 2 * p] = __byte_perm(a, b, 0x5410);
        *(unsigned*)&Bl[bn_][bkh + 2 * p] = __byte_perm(a, b, 0x7632);
    }
}

// ---- GEMM1: h[z] = agg[z] @ Wa[z] + ba[z]; fused stats; reg double-buffer ----
__global__ __launch_bounds__(256) void k_gemm1(
    const float* __restrict__ ba, int M, int Kd, int Nd) {
    __shared__ __align__(16) __nv_bfloat16 Ah[BM][BKP], Al[BM][BKP];
    __shared__ __align__(16) __nv_bfloat16 Bh[BN][BKP], Bl[BN][BKP];
    __shared__ float sS[BN], sQ[BN];
    int z = blockIdx.z;
    const float* A = d_agg[z];
    const unsigned* B = d_wa_pk + (long)z * Kd * Nd;
    const float* bias = ba + z * Nd;
    float* C = d_hh[z];

    int tid = threadIdx.x;
    int lane = tid & 31, wid = tid >> 5;
    int wm = wid & 1, wn = wid >> 1;
    int gid = lane >> 2, tig = lane & 3;
    int row0 = blockIdx.y * BM;
    int col0 = blockIdx.x * BN;

    float acc[4][4][4];
#pragma unroll
    for (int a = 0; a < 4; a++)
#pragma unroll
        for (int b = 0; b < 4; b++)
#pragma unroll
            for (int r = 0; r < 4; r++) acc[a][b][r] = 0.f;

    int arow = tid >> 1, akq = (tid & 1) * 16;
    int grow = row0 + arow;
    int bn_ = tid & 127, bkh = (tid >> 7) * 16;
    int gn = col0 + bn_;

    float aR[16];
    unsigned wR[16];
    auto loadT = [&](int kt) {
#pragma unroll
        for (int jj = 0; jj < 16; jj++) {
            int ck = kt + akq + jj;
            aR[jj] = (grow < M && ck < Kd) ? A[(long)grow * Kd + ck] : 0.f;
        }
#pragma unroll
        for (int jj = 0; jj < 16; jj++) {
            int gk = kt + bkh + jj;
            wR[jj] = (gk < Kd && gn < Nd) ? B[(long)gk * Nd + gn] : 0u;
        }
    };

    int nk = (Kd + BK - 1) / BK;
    loadT(0);
    for (int t = 0; t < nk; t++) {
        sts_A(aR, Ah, Al, arow, akq);
        sts_B(wR, Bh, Bl, bn_, bkh);
        __syncthreads();
        if (t + 1 < nk) loadT((t + 1) * BK);   // prefetch hides under MMAs
        mma_slab(Ah, Al, Bh, Bl, acc, wm, wn, gid, tig);
        __syncthreads();
    }

    float colS[8], colQ[8];
#pragma unroll
    for (int i = 0; i < 8; i++) { colS[i] = 0.f; colQ[i] = 0.f; }
#pragma unroll
    for (int mi = 0; mi < 4; mi++)
#pragma unroll
        for (int nj = 0; nj < 4; nj++)
#pragma unroll
            for (int r = 0; r < 4; r++) {
                int row = row0 + wm * 64 + mi * 16 + gid + ((r >> 1) << 3);
                int col = col0 + wn * 32 + nj * 8 + 2 * tig + (r & 1);
                if (row < M && col < Nd) {
                    float vv = acc[mi][nj][r] + bias[col];
                    C[(long)row * Nd + col] = vv;
                    int ci2 = nj * 2 + (r & 1);
                    colS[ci2] += vv;
                    colQ[ci2] += vv * vv;
                }
            }
    if (tid < BN) { sS[tid] = 0.f; sQ[tid] = 0.f; }
    __syncthreads();
#pragma unroll
    for (int i = 0; i < 8; i++) {
        int lc = wn * 32 + (i >> 1) * 8 + 2 * tig + (i & 1);
        atomicAdd(&sS[lc], colS[i]);
        atomicAdd(&sQ[lc], colQ[i]);
    }
    __syncthreads();
    if (tid < BN) {
        int c = col0 + tid;
        if (c < Nd) {
            atomicAdd(&d_cs[z * 512 + c], sS[tid]);
            atomicAdd(&d_css[z * 512 + c], sQ[tid]);
        }
    }
}

// ---- GEMM2: dest = act( sum_z relu(BN(h[z])) @ Wb[z] + sum bb ) ----
__global__ __launch_bounds__(256) void k_gemm2(
    const float* __restrict__ bb, float* __restrict__ C,
    int M, int Kd, int Nd, int leaky) {
    __shared__ __align__(16) __nv_bfloat16 Ah[BM][BKP], Al[BM][BKP];
    __shared__ __align__(16) __nv_bfloat16 Bh[BN][BKP], Bl[BN][BKP];

    int tid = threadIdx.x;
    int lane = tid & 31, wid = tid >> 5;
    int wm = wid & 1, wn = wid >> 1;
    int gid = lane >> 2, tig = lane & 3;
    int row0 = blockIdx.y * BM;
    int col0 = blockIdx.x * BN;

    float acc[4][4][4];
#pragma unroll
    for (int a = 0; a < 4; a++)
#pragma unroll
        for (int b = 0; b < 4; b++)
#pragma unroll
            for (int r = 0; r < 4; r++) acc[a][b][r] = 0.f;

    int arow = tid >> 1, akq = (tid & 1) * 16;
    int grow = row0 + arow;
    int bn_ = tid & 127, bkh = (tid >> 7) * 16;
    int gn = col0 + bn_;

    int ktiles = (Kd + BK - 1) / BK;
    int T = KT * ktiles;

    float aR[16];
    unsigned wR[16];
    auto loadT = [&](int t) {
        int z = t / ktiles;
        int kt = (t % ktiles) * BK;
        const float* A = d_hh[z];
        const float* sc = &d_scale[z * 512];
        const float* sh = &d_shift[z * 512];
        const unsigned* B = d_wb_pk + (long)z * Kd * Nd;
#pragma unroll
        for (int jj = 0; jj < 16; jj++) {
            int ck = kt + akq + jj;
            float vv = 0.f;
            if (grow < M && ck < Kd)
                vv = fmaxf(fmaf(A[(long)grow * Kd + ck], sc[ck], sh[ck]), 0.f);
            aR[jj] = vv;
        }
#pragma unroll
        for (int jj = 0; jj < 16; jj++) {
            int gk = kt + bkh + jj;
            wR[jj] = (gk < Kd && gn < Nd) ? B[(long)gk * Nd + gn] : 0u;
        }
    };

    loadT(0);
    for (int t = 0; t < T; t++) {
        sts_A(aR, Ah, Al, arow, akq);
        sts_B(wR, Bh, Bl, bn_, bkh);
        __syncthreads();
        if (t + 1 < T) loadT(t + 1);
        mma_slab(Ah, Al, Bh, Bl, acc, wm, wn, gid, tig);
        __syncthreads();
    }

#pragma unroll
    for (int mi = 0; mi < 4; mi++)
#pragma unroll
        for (int nj = 0; nj < 4; nj++)
#pragma unroll
            for (int r = 0; r < 4; r++) {
                int row = row0 + wm * 64 + mi * 16 + gid + ((r >> 1) << 3);
                int col = col0 + wn * 32 + nj * 8 + 2 * tig + (r & 1);
                if (row < M && col < Nd) {
                    float vv = acc[mi][nj][r] + bb[col] + bb[Nd + col] +
                               bb[2 * Nd + col];
                    if (leaky) vv = (vv > 0.f) ? vv : 0.01f * vv;
                    C[(long)row * Nd + col] = vv;
                }
            }
}

// ---------------- BN finalize ----------------
__global__ void k_bnfinal(const float* __restrict__ gB,
                          const float* __restrict__ btB, int C) {
    int k = blockIdx.x;
    int c = threadIdx.x;
    if (c >= C) return;
    float mu  = d_cs[k * 512 + c] / (float)NN;
    float var = d_css[k * 512 + c] / (float)NN - mu * mu;
    var = fmaxf(var, 0.f);
    float s = gB[k * C + c] * rsqrtf(var + BN_EPS);
    d_scale[k * 512 + c] = s;
    d_shift[k * 512 + c] = btB[k * C + c] - mu * s;
}

// ---------------- launch ----------------
extern "C" void kernel_launch(void* const* d_in, const int* in_sizes, int n_in,
                              void* d_out, int out_size) {
    // GB300 ATS pitfall: resolve REAL device addresses of __device__ symbols.
    float* p_xcur;
    unsigned *p_wa, *p_wb;
    cudaGetSymbolAddress((void**)&p_xcur, d_xcur);
    cudaGetSymbolAddress((void**)&p_wa, d_wa_pk);
    cudaGetSymbolAddress((void**)&p_wb, d_wb_pk);

    const float* x  = (const float*)d_in[0];
    const int*   ei = (const int*)d_in[1];
    const float* ea = (const float*)d_in[2];

    const int ciL[3] = {170, 256, 256};
    const int chL[3] = {340, 512, 512};
    const int co = 256;

    k_count<<<(KT * NE + 255) / 256, 256>>>(ei);
    k_scan<<<KT, 1024>>>();
    k_fill<<<(KT * NE + 255) / 256, 256>>>(ei);

    const float* xin = x;
    for (int l = 0; l < 3; l++) {
        int ci = ciL[l], ch = chL[l];
        const float* We = (const float*)d_in[3 + l * 8 + 0];
        const float* be = (const float*)d_in[3 + l * 8 + 1];
        const float* Wa = (const float*)d_in[3 + l * 8 + 2];
        const float* ba = (const float*)d_in[3 + l * 8 + 3];
        const float* g  = (const float*)d_in[3 + l * 8 + 4];
        const float* bt = (const float*)d_in[3 + l * 8 + 5];
        const float* Wb = (const float*)d_in[3 + l * 8 + 6];
        const float* bb = (const float*)d_in[3 + l * 8 + 7];
        float* dest = (l == 2) ? (float*)d_out : p_xcur;

        int na = KT * ci * ch, nb = KT * ch * co;
        k_wsplit<<<(na + 255) / 256, 256>>>(Wa, p_wa, na);
        k_wsplit<<<(nb + 255) / 256, 256>>>(Wb, p_wb, nb);

        dim3 ga(NN, KT);
        k_aggr<<<ga, 256>>>(xin, ei, ea, We, be, ci);

        dim3 g1((ch + BN - 1) / BN, (NN + BM - 1) / BM, KT);
        k_gemm1<<<g1, 256>>>(ba, NN, ci, ch);

        k_bnfinal<<<KT, 512>>>(g, bt, ch);

        dim3 g2((co + BN - 1) / BN, (NN + BM - 1) / BM);
        k_gemm2<<<g2, 256>>>(bb, dest, NN, ch, co, (l < 2) ? 1 : 0);

        if (l < 2) xin = p_xcur;
    }
}